// round 11
// baseline (speedup 1.0000x reference)
#include <cuda_runtime.h>
#include <math.h>

// out[b][i] = cos(theta_i) * Z_i / T
//   T   = sum_k x_k^2 (NaN-scrubbed),  Z_i = sum_k sign_i(k) x_k^2,
//   sign_i(k) = +1 if bit (3-i) of k == 0  (wire 0 = MSB).
//
// PERSISTENT quad-cooperative kernel: 304 CTAs x 512 threads (2 CTAs/SM on
// 152 SMs) grid-stride over 32-sample tiles. Per-warp setup (cosf, signs,
// lane math) runs ONCE; no wave transitions; L1 persists across tiles.
//
// Per tile: 4 front-batched warp-contiguous LDG.128 (512B each).
// Element k = (lane&3)*4 + comp:
//   k bit3 = lane bit1 (wire 0), k bit2 = lane bit0 (wire 1),
//   k bits 1:0 = component bits (wires 2,3).
// 4 shuffles/group; lane j emits wire j^2, writes out[lane^2] (coalesced).
// NaN scrub: fmaxf(x*x,0) == x*x for non-NaN (>=0), == 0 for NaN.
// cos via __cosf (|err| ~1e-6 << 1e-3 tolerance).
__global__ void __launch_bounds__(512) quantum_z_kernel(
    const float4* __restrict__ x, float* __restrict__ out,
    const float* __restrict__ qw, int nTiles)
{
    int lane   = threadIdx.x & 31;
    int gwarp  = (blockIdx.x * blockDim.x + threadIdx.x) >> 5;
    int nwarps = (gridDim.x * blockDim.x) >> 5;

    int  j   = lane & 3;
    float c  = __cosf(qw[j ^ 2]);   // lane j emits wire j^2
    bool odd = (lane & 1);
    bool is1 = (j == 1), is2 = (j == 2), is3 = (j == 3);
    int  outLane = lane ^ 2;

    for (int tile = gwarp; tile < nTiles; tile += nwarps) {
        const float4* base = x + (size_t)tile * 128;   // 32 samples * 4 f4
        float* obase = out + (size_t)tile * 128 + outLane;

        float4 v[4];
        #pragma unroll
        for (int g = 0; g < 4; ++g) v[g] = __ldcs(&base[g * 32 + lane]);

        #pragma unroll
        for (int g = 0; g < 4; ++g) {
            float s0 = fmaxf(v[g].x * v[g].x, 0.0f);
            float s1 = fmaxf(v[g].y * v[g].y, 0.0f);
            float s2 = fmaxf(v[g].z * v[g].z, 0.0f);
            float s3 = fmaxf(v[g].w * v[g].w, 0.0f);

            float p01 = s0 + s1, p23 = s2 + s3;
            float t     = p01 + p23;
            float z2loc = p01 - p23;               // wire 2 (comp bit1)
            float z3loc = (s0 - s1) + (s2 - s3);   // wire 3 (comp bit0)

            // Stage 1 over lane bit0
            float sh1 = __shfl_xor_sync(0xFFFFFFFFu, t, 1);
            float tp  = t + sh1;                   // pair sum
            float z1p = sh1 - t;                   // wire-1 partial (odd)

            float w   = odd ? z2loc : z3loc;       // payload swap
            float sh4 = __shfl_xor_sync(0xFFFFFFFFu, w, 1);
            float m   = (odd ? z3loc : z2loc) + sh4;

            // Stage 2 over lane bit1
            float sh2 = __shfl_xor_sync(0xFFFFFFFFu, tp, 2);
            float T   = tp + sh2;
            // lane j=2: Z0 = sh2 - tp

            float send  = is1 ? z1p : m;
            float recv2 = __shfl_xor_sync(0xFFFFFFFFu, send, 2);
            // j0: m+recv2 = Z2;  j1: m+recv2 = Z3;  j3: z1p+recv2 = Z1
            float Zacc = (is3 ? z1p : m) + recv2;
            float Z    = is2 ? (sh2 - tp) : Zacc;

            obase[g * 32] = c * __fdividef(Z, T);
        }
    }
}

extern "C" void kernel_launch(void* const* d_in, const int* in_sizes, int n_in,
                              void* d_out, int out_size) {
    const float* x  = (const float*)d_in[0];
    const float* qw = (const float*)d_in[1];
    float* out = (float*)d_out;

    int B = in_sizes[0] / 16;                 // 2^21 samples
    int nTiles = B / 32;                      // 65536 tiles of 32 samples

    // Persistent: 2 CTAs per SM (152 SMs on GB300), 512 threads each.
    int blocks = 304;
    quantum_z_kernel<<<blocks, 512>>>(
        (const float4*)x, out, qw, nTiles);
}

// round 12
// speedup vs baseline: 1.0503x; 1.0503x over previous
#include <cuda_runtime.h>
#include <math.h>

// out[b][i] = cos(theta_i) * Z_i / T
//   T   = sum_k x_k^2 (NaN-scrubbed),  Z_i = sum_k sign_i(k) x_k^2,
//   sign_i(k) = +1 if bit (3-i) of k == 0  (wire 0 = MSB).
//
// PERSISTENT quad-cooperative kernel, 608 CTAs x 512 threads: ~3 CTAs/SM
// resident (48 warps/SM, ~75% occ — matches R10) and zero wave
// transitions. R11's regression was launch geometry (304 blocks -> 2
// CTAs/SM -> 48.6% occ), not the persistence itself.
//
// Per tile: 4 front-batched warp-contiguous LDG.128 (512B each).
// Element k = (lane&3)*4 + comp:
//   k bit3 = lane bit1 (wire 0), k bit2 = lane bit0 (wire 1),
//   k bits 1:0 = component bits (wires 2,3).
// 4 shuffles/group; lane j emits wire j^2, writes out[lane^2] (coalesced).
// NaN scrub: fmaxf(x*x,0) == x*x for non-NaN (>=0), == 0 for NaN.
// cos via __cosf (|err| ~1e-6 << 1e-3 tolerance).
__global__ void __launch_bounds__(512) quantum_z_kernel(
    const float4* __restrict__ x, float* __restrict__ out,
    const float* __restrict__ qw, int nTiles)
{
    int lane   = threadIdx.x & 31;
    int gwarp  = (blockIdx.x * blockDim.x + threadIdx.x) >> 5;
    int nwarps = (gridDim.x * blockDim.x) >> 5;

    int  j   = lane & 3;
    float c  = __cosf(qw[j ^ 2]);   // lane j emits wire j^2
    bool odd = (lane & 1);
    bool is1 = (j == 1), is2 = (j == 2), is3 = (j == 3);
    int  outLane = lane ^ 2;

    for (int tile = gwarp; tile < nTiles; tile += nwarps) {
        const float4* base = x + (size_t)tile * 128;   // 32 samples * 4 f4
        float* obase = out + (size_t)tile * 128 + outLane;

        float4 v[4];
        #pragma unroll
        for (int g = 0; g < 4; ++g) v[g] = __ldcs(&base[g * 32 + lane]);

        #pragma unroll
        for (int g = 0; g < 4; ++g) {
            float s0 = fmaxf(v[g].x * v[g].x, 0.0f);
            float s1 = fmaxf(v[g].y * v[g].y, 0.0f);
            float s2 = fmaxf(v[g].z * v[g].z, 0.0f);
            float s3 = fmaxf(v[g].w * v[g].w, 0.0f);

            float p01 = s0 + s1, p23 = s2 + s3;
            float t     = p01 + p23;
            float z2loc = p01 - p23;               // wire 2 (comp bit1)
            float z3loc = (s0 - s1) + (s2 - s3);   // wire 3 (comp bit0)

            // Stage 1 over lane bit0
            float sh1 = __shfl_xor_sync(0xFFFFFFFFu, t, 1);
            float tp  = t + sh1;                   // pair sum
            float z1p = sh1 - t;                   // wire-1 partial (odd)

            float w   = odd ? z2loc : z3loc;       // payload swap
            float sh4 = __shfl_xor_sync(0xFFFFFFFFu, w, 1);
            float m   = (odd ? z3loc : z2loc) + sh4;

            // Stage 2 over lane bit1
            float sh2 = __shfl_xor_sync(0xFFFFFFFFu, tp, 2);
            float T   = tp + sh2;
            // lane j=2: Z0 = sh2 - tp

            float send  = is1 ? z1p : m;
            float recv2 = __shfl_xor_sync(0xFFFFFFFFu, send, 2);
            // j0: m+recv2 = Z2;  j1: m+recv2 = Z3;  j3: z1p+recv2 = Z1
            float Zacc = (is3 ? z1p : m) + recv2;
            float Z    = is2 ? (sh2 - tp) : Zacc;

            obase[g * 32] = c * __fdividef(Z, T);
        }
    }
}

extern "C" void kernel_launch(void* const* d_in, const int* in_sizes, int n_in,
                              void* d_out, int out_size) {
    const float* x  = (const float*)d_in[0];
    const float* qw = (const float*)d_in[1];
    float* out = (float*)d_out;

    int B = in_sizes[0] / 16;                 // 2^21 samples
    int nTiles = B / 32;                      // 65536 tiles of 32 samples

    // Persistent: 608 CTAs (~3 resident/SM at 39 regs -> ~48 warps/SM).
    int blocks = 608;
    quantum_z_kernel<<<blocks, 512>>>(
        (const float4*)x, out, qw, nTiles);
}

// round 13
// speedup vs baseline: 1.0602x; 1.0094x over previous
#include <cuda_runtime.h>
#include <math.h>

// out[b][i] = cos(theta_i) * Z_i / T
//   T   = sum_k x_k^2 (NaN-scrubbed),  Z_i = sum_k sign_i(k) x_k^2,
//   sign_i(k) = +1 if bit (3-i) of k == 0  (wire 0 = MSB).
//
// Quad-cooperative, warp tile = 32 samples: 4 front-batched LDG.128, each
// warp-contiguous (512B). Element k = (lane&3)*4 + comp:
//   k bit3 = lane bit1 (wire 0), k bit2 = lane bit0 (wire 1),
//   k bits 1:0 = component bits (wires 2,3).
//
// 4 shuffles/group:
//  S1a: shfl(t,1)  -> pair-sum tp AND z1p = sh1 - t
//  S1b: payload swap (even sends z3loc, odd z2loc) -> m = Z2/Z3 pair
//  S2a: shfl(tp,2) -> T everywhere; Z0 = sh2 - tp free for lane j=2
//  S2b: payload swap (j==1 sends z1p, else m) -> Z2 (j0), Z3 (j1), Z1 (j3)
// Lane j emits wire j^2, writes out[lane^2] (128B coalesced store).
// NaN scrub: fmaxf(x*x,0) == x*x for non-NaN (>=0), == 0 for NaN.
// cos via __cosf (1 MUFU/thread; |err| ~1e-6 << 1e-3 tolerance).
//
// 1024-thread blocks, 2048 CTAs: half of R10's CTA count (the R9->R10
// halving won 0.45us), __launch_bounds__(1024,2) pins regs <=32 so
// 2 CTAs/SM = 64 warps/SM (full) fit. Non-persistent (R11/R12 disproved).
__global__ void __launch_bounds__(1024, 2) quantum_z_kernel(
    const float4* __restrict__ x, float* __restrict__ out,
    const float* __restrict__ qw, int B)
{
    int gtid   = blockIdx.x * blockDim.x + threadIdx.x;
    int warpId = gtid >> 5;
    int lane   = threadIdx.x & 31;

    if (warpId * 32 >= B) return;   // warp tile = 32 samples (B % 32 == 0)

    const float4* base = x + (size_t)warpId * 128;        // 32 samples * 4 f4
    float* obase = out + (size_t)warpId * 128 + (lane ^ 2);

    float4 v[4];
    #pragma unroll
    for (int g = 0; g < 4; ++g) v[g] = __ldcs(&base[g * 32 + lane]);

    int  j   = lane & 3;
    float c  = __cosf(qw[j ^ 2]);   // lane j emits wire j^2
    bool odd = (lane & 1);
    bool is1 = (j == 1), is2 = (j == 2), is3 = (j == 3);

    #pragma unroll
    for (int g = 0; g < 4; ++g) {
        float s0 = fmaxf(v[g].x * v[g].x, 0.0f);
        float s1 = fmaxf(v[g].y * v[g].y, 0.0f);
        float s2 = fmaxf(v[g].z * v[g].z, 0.0f);
        float s3 = fmaxf(v[g].w * v[g].w, 0.0f);

        float p01 = s0 + s1, p23 = s2 + s3;
        float t     = p01 + p23;
        float z2loc = p01 - p23;               // wire 2 (comp bit1)
        float z3loc = (s0 - s1) + (s2 - s3);   // wire 3 (comp bit0)

        // Stage 1 over lane bit0
        float sh1 = __shfl_xor_sync(0xFFFFFFFFu, t, 1);
        float tp  = t + sh1;                   // pair sum
        float z1p = sh1 - t;                   // wire-1 partial (odd lanes)

        float w   = odd ? z2loc : z3loc;       // payload swap
        float sh4 = __shfl_xor_sync(0xFFFFFFFFu, w, 1);
        float m   = (odd ? z3loc : z2loc) + sh4;   // even: Z2-pair, odd: Z3-pair

        // Stage 2 over lane bit1
        float sh2 = __shfl_xor_sync(0xFFFFFFFFu, tp, 2);
        float T   = tp + sh2;
        // lane j=2 (bit1=1): Z0 = sh2 - tp

        float send  = is1 ? z1p : m;           // j1->z1p (for j3); others->m
        float recv2 = __shfl_xor_sync(0xFFFFFFFFu, send, 2);
        // j0: m+recv2 = Z2;  j1: m+recv2 = Z3;  j3: z1p+recv2 = Z1
        float Zacc = (is3 ? z1p : m) + recv2;
        float Z    = is2 ? (sh2 - tp) : Zacc;

        obase[g * 32] = c * __fdividef(Z, T);
    }
}

extern "C" void kernel_launch(void* const* d_in, const int* in_sizes, int n_in,
                              void* d_out, int out_size) {
    const float* x  = (const float*)d_in[0];
    const float* qw = (const float*)d_in[1];
    float* out = (float*)d_out;

    int B = in_sizes[0] / 16;                 // 2^21 samples
    // 32 samples/warp, 32 warps/block -> 1024 samples per block.
    int blocks = (B + 1023) / 1024;

    quantum_z_kernel<<<blocks, 1024>>>(
        (const float4*)x, out, qw, B);
}